// round 8
// baseline (speedup 1.0000x reference)
#include <cuda_runtime.h>
#include <stdint.h>

// BFP quantizer: x (64, 256, 56, 56) fp32 NCHW, tile=8 along C (axis 1).
// bitwidth=16 -> m=7, qmax=127, step=2^(shared_exp-6).
// shared_exp = floor(log2(max(|x| over tile), eps)), eps=2^-23.
//
// FINAL (= R6/R2, best of a 7-point sweep: kernel 56.7us, DRAM 79.3%,
// 6.28 TB/s on a 50/50 r/w stream — the demonstrated mixed-stream ceiling).
// Sweep findings:
//   - warp-dense vector accesses mandatory (strided pairs: -36%)
//   - __ldcs/__stcs best cache policy (__stwt: -3%; default: -1%)
//   - occupancy 20-60%, MLP 8-16, block 256/512, persistence: all neutral
//
// Thread = (n, c_tile, w), covers float4 positions w and w+392 across all
// 8 channels of the tile: 16 front-batched streaming LDG.128, each with
// warp lanes at consecutive 16B (fully dense wavefronts).
// Exact math: shared_exp via IEEE exponent bits (maxabs clamped to eps is
// always normal), rintf = round-half-even, step/inv_step bit-constructed
// powers of two (exponents always in normal range).

#define N_DIM   64
#define C_DIM   256
#define HW_DIM  3136               // 56*56
#define TILE_C  8
#define NTILES  (C_DIM / TILE_C)   // 32
#define HW4     (HW_DIM / 4)       // 784
#define HW8     (HW4 / 2)          // 392
#define EPS_F   1.1920928955078125e-07f  // 2^-23

__global__ __launch_bounds__(256, 2)
void bfp_quant_kernel(const float4* __restrict__ in, float4* __restrict__ out)
{
    int t = blockIdx.x * blockDim.x + threadIdx.x;
    // t in [0, N*NTILES*HW8)
    int w    = t % HW8;
    int rest = t / HW8;
    int ct   = rest % NTILES;
    int n    = rest / NTILES;

    long base = (long)n * (C_DIM * HW4) + (long)ct * (TILE_C * HW4) + w;

    // Front-batched: 16 streaming LDG.128
    float a[TILE_C][2][4];
    #pragma unroll
    for (int k = 0; k < TILE_C; k++) {
        float4 v0 = __ldcs(&in[base + (long)k * HW4]);
        float4 v1 = __ldcs(&in[base + (long)k * HW4 + HW8]);
        a[k][0][0] = v0.x; a[k][0][1] = v0.y; a[k][0][2] = v0.z; a[k][0][3] = v0.w;
        a[k][1][0] = v1.x; a[k][1][1] = v1.y; a[k][1][2] = v1.z; a[k][1][3] = v1.w;
    }

    #pragma unroll
    for (int g = 0; g < 2; g++) {
        #pragma unroll
        for (int j = 0; j < 4; j++) {
            // tile max(|x|) clamped by eps
            float mx = EPS_F;
            #pragma unroll
            for (int k = 0; k < TILE_C; k++)
                mx = fmaxf(mx, fabsf(a[k][g][j]));

            // shared_exp = floor(log2(mx)): exponent bits (mx normal, >0)
            int e = (int)(__float_as_uint(mx) >> 23) - 127;

            // inv_step = 2^(6-e), step = 2^(e-6), both always normal
            float inv_step = __uint_as_float((uint32_t)(133 - e) << 23);
            float step     = __uint_as_float((uint32_t)(e + 121) << 23);

            #pragma unroll
            for (int k = 0; k < TILE_C; k++) {
                float q = rintf(a[k][g][j] * inv_step);   // round-half-even
                q = fminf(fmaxf(q, -127.0f), 127.0f);
                a[k][g][j] = q * step;
            }
        }
    }

    #pragma unroll
    for (int k = 0; k < TILE_C; k++) {
        float4 v0, v1;
        v0.x = a[k][0][0]; v0.y = a[k][0][1]; v0.z = a[k][0][2]; v0.w = a[k][0][3];
        v1.x = a[k][1][0]; v1.y = a[k][1][1]; v1.z = a[k][1][2]; v1.w = a[k][1][3];
        __stcs(&out[base + (long)k * HW4], v0);
        __stcs(&out[base + (long)k * HW4 + HW8], v1);
    }
}

extern "C" void kernel_launch(void* const* d_in, const int* in_sizes, int n_in,
                              void* d_out, int out_size)
{
    const float4* in  = (const float4*)d_in[0];
    float4*       out = (float4*)d_out;

    const int total_threads = N_DIM * NTILES * HW8;   // 802,816
    const int block = 256;
    const int grid  = total_threads / block;          // 3136 exactly

    bfp_quant_kernel<<<grid, block>>>(in, out);
}

// round 9
// speedup vs baseline: 1.0329x; 1.0329x over previous
#include <cuda_runtime.h>
#include <stdint.h>

// BFP quantizer: x (64, 256, 56, 56) fp32 NCHW, tile=8 along C (axis 1).
// bitwidth=16 -> m=7, qmax=127, step=2^(shared_exp-6).
// shared_exp = floor(log2(max(|x| over tile), eps)), eps=2^-23.
//
// FINAL (= R6/R2 source, unchanged). Best measured: kernel 56.7us,
// DRAM 79.3% (6.28 TB/s) on a 50/50 r/w stream. R8 ran this exact source
// at 64.3us / DRAM 70% — environmental clock-state variance, not code.
// Sweep findings (7 configs):
//   - warp-dense vector accesses mandatory (strided pairs: -36%, real)
//   - persistent grid-stride worse (-6%, real)
//   - __ldcs/__stcs >= default > __stwt
//   - occupancy 20-60%, MLP 8-16, block 256/512: within noise
//
// Thread = (n, c_tile, w), covers float4 positions w and w+392 across all
// 8 channels of the tile: 16 front-batched streaming LDG.128, each with
// warp lanes at consecutive 16B (fully dense wavefronts).
// Exact math: shared_exp via IEEE exponent bits (maxabs clamped to eps is
// always normal), rintf = round-half-even, step/inv_step bit-constructed
// powers of two (exponents always in normal range).

#define N_DIM   64
#define C_DIM   256
#define HW_DIM  3136               // 56*56
#define TILE_C  8
#define NTILES  (C_DIM / TILE_C)   // 32
#define HW4     (HW_DIM / 4)       // 784
#define HW8     (HW4 / 2)          // 392
#define EPS_F   1.1920928955078125e-07f  // 2^-23

__global__ __launch_bounds__(256, 2)
void bfp_quant_kernel(const float4* __restrict__ in, float4* __restrict__ out)
{
    int t = blockIdx.x * blockDim.x + threadIdx.x;
    // t in [0, N*NTILES*HW8)
    int w    = t % HW8;
    int rest = t / HW8;
    int ct   = rest % NTILES;
    int n    = rest / NTILES;

    long base = (long)n * (C_DIM * HW4) + (long)ct * (TILE_C * HW4) + w;

    // Front-batched: 16 streaming LDG.128
    float a[TILE_C][2][4];
    #pragma unroll
    for (int k = 0; k < TILE_C; k++) {
        float4 v0 = __ldcs(&in[base + (long)k * HW4]);
        float4 v1 = __ldcs(&in[base + (long)k * HW4 + HW8]);
        a[k][0][0] = v0.x; a[k][0][1] = v0.y; a[k][0][2] = v0.z; a[k][0][3] = v0.w;
        a[k][1][0] = v1.x; a[k][1][1] = v1.y; a[k][1][2] = v1.z; a[k][1][3] = v1.w;
    }

    #pragma unroll
    for (int g = 0; g < 2; g++) {
        #pragma unroll
        for (int j = 0; j < 4; j++) {
            // tile max(|x|) clamped by eps
            float mx = EPS_F;
            #pragma unroll
            for (int k = 0; k < TILE_C; k++)
                mx = fmaxf(mx, fabsf(a[k][g][j]));

            // shared_exp = floor(log2(mx)): exponent bits (mx normal, >0)
            int e = (int)(__float_as_uint(mx) >> 23) - 127;

            // inv_step = 2^(6-e), step = 2^(e-6), both always normal
            float inv_step = __uint_as_float((uint32_t)(133 - e) << 23);
            float step     = __uint_as_float((uint32_t)(e + 121) << 23);

            #pragma unroll
            for (int k = 0; k < TILE_C; k++) {
                float q = rintf(a[k][g][j] * inv_step);   // round-half-even
                q = fminf(fmaxf(q, -127.0f), 127.0f);
                a[k][g][j] = q * step;
            }
        }
    }

    #pragma unroll
    for (int k = 0; k < TILE_C; k++) {
        float4 v0, v1;
        v0.x = a[k][0][0]; v0.y = a[k][0][1]; v0.z = a[k][0][2]; v0.w = a[k][0][3];
        v1.x = a[k][1][0]; v1.y = a[k][1][1]; v1.z = a[k][1][2]; v1.w = a[k][1][3];
        __stcs(&out[base + (long)k * HW4], v0);
        __stcs(&out[base + (long)k * HW4 + HW8], v1);
    }
}

extern "C" void kernel_launch(void* const* d_in, const int* in_sizes, int n_in,
                              void* d_out, int out_size)
{
    const float4* in  = (const float4*)d_in[0];
    float4*       out = (float4*)d_out;

    const int total_threads = N_DIM * NTILES * HW8;   // 802,816
    const int block = 256;
    const int grid  = total_threads / block;          // 3136 exactly

    bfp_quant_kernel<<<grid, block>>>(in, out);
}

// round 10
// speedup vs baseline: 1.0370x; 1.0040x over previous
#include <cuda_runtime.h>
#include <stdint.h>

// BFP quantizer: x (64, 256, 56, 56) fp32 NCHW, tile=8 along C (axis 1).
// bitwidth=16 -> m=7, qmax=127, step=2^(shared_exp-6).
// shared_exp = floor(log2(max(|x| over tile), eps)), eps=2^-23.
//
// FINAL (= R6 source, unchanged; 3 good-state reproductions: 56.70 / 56.96
// / 57.09 us kernel, DRAM 78.5-79.3%, 6.2-6.3 TB/s on a 50/50 r/w stream —
// the demonstrated mixed-stream HBM ceiling for this chip). R8's 64.3us on
// identical binary was an environmental clock-state excursion.
// Sweep findings (8 configs):
//   - warp-dense vector accesses mandatory (strided pairs: -36%, real)
//   - persistent grid-stride worse (-6%, real)
//   - __ldcs/__stcs >= default > __stwt
//   - occupancy 20-60%, MLP 8-16, block 256/512: within noise
//
// Thread = (n, c_tile, w), covers float4 positions w and w+392 across all
// 8 channels of the tile: 16 front-batched streaming LDG.128, each with
// warp lanes at consecutive 16B (fully dense wavefronts).
// Exact math: shared_exp via IEEE exponent bits (maxabs clamped to eps is
// always normal), rintf = round-half-even, step/inv_step bit-constructed
// powers of two (exponents always in normal range). rel_err = 0.0.

#define N_DIM   64
#define C_DIM   256
#define HW_DIM  3136               // 56*56
#define TILE_C  8
#define NTILES  (C_DIM / TILE_C)   // 32
#define HW4     (HW_DIM / 4)       // 784
#define HW8     (HW4 / 2)          // 392
#define EPS_F   1.1920928955078125e-07f  // 2^-23

__global__ __launch_bounds__(256, 2)
void bfp_quant_kernel(const float4* __restrict__ in, float4* __restrict__ out)
{
    int t = blockIdx.x * blockDim.x + threadIdx.x;
    // t in [0, N*NTILES*HW8)
    int w    = t % HW8;
    int rest = t / HW8;
    int ct   = rest % NTILES;
    int n    = rest / NTILES;

    long base = (long)n * (C_DIM * HW4) + (long)ct * (TILE_C * HW4) + w;

    // Front-batched: 16 streaming LDG.128
    float a[TILE_C][2][4];
    #pragma unroll
    for (int k = 0; k < TILE_C; k++) {
        float4 v0 = __ldcs(&in[base + (long)k * HW4]);
        float4 v1 = __ldcs(&in[base + (long)k * HW4 + HW8]);
        a[k][0][0] = v0.x; a[k][0][1] = v0.y; a[k][0][2] = v0.z; a[k][0][3] = v0.w;
        a[k][1][0] = v1.x; a[k][1][1] = v1.y; a[k][1][2] = v1.z; a[k][1][3] = v1.w;
    }

    #pragma unroll
    for (int g = 0; g < 2; g++) {
        #pragma unroll
        for (int j = 0; j < 4; j++) {
            // tile max(|x|) clamped by eps
            float mx = EPS_F;
            #pragma unroll
            for (int k = 0; k < TILE_C; k++)
                mx = fmaxf(mx, fabsf(a[k][g][j]));

            // shared_exp = floor(log2(mx)): exponent bits (mx normal, >0)
            int e = (int)(__float_as_uint(mx) >> 23) - 127;

            // inv_step = 2^(6-e), step = 2^(e-6), both always normal
            float inv_step = __uint_as_float((uint32_t)(133 - e) << 23);
            float step     = __uint_as_float((uint32_t)(e + 121) << 23);

            #pragma unroll
            for (int k = 0; k < TILE_C; k++) {
                float q = rintf(a[k][g][j] * inv_step);   // round-half-even
                q = fminf(fmaxf(q, -127.0f), 127.0f);
                a[k][g][j] = q * step;
            }
        }
    }

    #pragma unroll
    for (int k = 0; k < TILE_C; k++) {
        float4 v0, v1;
        v0.x = a[k][0][0]; v0.y = a[k][0][1]; v0.z = a[k][0][2]; v0.w = a[k][0][3];
        v1.x = a[k][1][0]; v1.y = a[k][1][1]; v1.z = a[k][1][2]; v1.w = a[k][1][3];
        __stcs(&out[base + (long)k * HW4], v0);
        __stcs(&out[base + (long)k * HW4 + HW8], v1);
    }
}

extern "C" void kernel_launch(void* const* d_in, const int* in_sizes, int n_in,
                              void* d_out, int out_size)
{
    const float4* in  = (const float4*)d_in[0];
    float4*       out = (float4*)d_out;

    const int total_threads = N_DIM * NTILES * HW8;   // 802,816
    const int block = 256;
    const int grid  = total_threads / block;          // 3136 exactly

    bfp_quant_kernel<<<grid, block>>>(in, out);
}